// round 6
// baseline (speedup 1.0000x reference)
#include <cuda_runtime.h>

#define MAT 16384
#define SCALE (1.0f/16384.0f)   // 1/(N * N_HEAD)
#define SA  132                 // A smem row stride
#define SBN 136                 // B smem row stride
#define NB  128                 // persistent grid size (<= SM count)

// ---------------- scratch (device globals) ----------------
__device__ __align__(16) float g_part[16 * 8 * MAT];   // 8 MB G0 partials
__device__ __align__(16) float g_G[2][8 * MAT];
__device__ __align__(16) float g_R[8 * MAT];
__device__ __align__(16) float g_Wp[64 * MAT];          // per-head W
__device__ __align__(16) float g_Wq[8 * MAT];           // summed W'
__device__ __align__(16) float g_U[8 * MAT];            // U = G @ W'
__device__ unsigned g_cnt = 0;
__device__ unsigned g_gen = 0;

// ---------------- grid barrier (generation counter) ----------------
__device__ __forceinline__ void gsync(unsigned target) {
    __syncthreads();
    if (threadIdx.x == 0) {
        __threadfence();
        unsigned old = atomicAdd(&g_cnt, 1u);
        if (old == NB - 1) {
            atomicExch(&g_cnt, 0u);
            __threadfence();
            atomicAdd(&g_gen, 1u);
        } else {
            volatile unsigned* vg = &g_gen;
            while ((int)(*vg - target) < 0) { __nanosleep(32); }
        }
        __threadfence();
    }
    __syncthreads();
}

// ---------------- tf32 helpers ----------------
__device__ __forceinline__ float tf(float x) {
    float y; asm("cvt.rna.tf32.f32 %0, %1;" : "=f"(y) : "f"(x)); return y;
}
__device__ __forceinline__ float4 tf4(float4 x) {
    x.x = tf(x.x); x.y = tf(x.y); x.z = tf(x.z); x.w = tf(x.w); return x;
}
__device__ __forceinline__ void mma8(float c[4], const float a[4], const float b[2]) {
    asm volatile(
        "mma.sync.aligned.m16n8k8.row.col.f32.tf32.tf32.f32 "
        "{%0,%1,%2,%3}, {%4,%5,%6,%7}, {%8,%9}, {%0,%1,%2,%3};"
        : "+f"(c[0]), "+f"(c[1]), "+f"(c[2]), "+f"(c[3])
        : "r"(__float_as_uint(a[0])), "r"(__float_as_uint(a[1])),
          "r"(__float_as_uint(a[2])), "r"(__float_as_uint(a[3])),
          "r"(__float_as_uint(b[0])), "r"(__float_as_uint(b[1])));
}

// ---------------- smem fills (512 threads) ----------------
__device__ __forceinline__ void fillA64(const float* __restrict__ A, int lda,
                                        float* __restrict__ As) {
#pragma unroll
    for (int i = 0; i < 4; i++) {
        int idx = threadIdx.x + 512 * i;
        int m = idx >> 5, kf = (idx & 31) * 4;
        *(float4*)(As + m * SA + kf) = tf4(*(const float4*)(A + m * lda + kf));
    }
}
__device__ __forceinline__ void fillA128(const float* __restrict__ A, int lda,
                                         float* __restrict__ As) {
#pragma unroll
    for (int i = 0; i < 8; i++) {
        int idx = threadIdx.x + 512 * i;
        int m = idx >> 5, kf = (idx & 31) * 4;
        *(float4*)(As + m * SA + kf) = tf4(*(const float4*)(A + m * lda + kf));
    }
}
// As[m][k] = tf(A[k*lda + m])  (transposed source, 128x128)
__device__ __forceinline__ void fillAT128(const float* __restrict__ A, int lda,
                                          float* __restrict__ As) {
#pragma unroll
    for (int i = 0; i < 8; i++) {
        int idx = threadIdx.x + 512 * i;
        int k = idx >> 5, mf = (idx & 31) * 4;
        float4 x = tf4(*(const float4*)(A + k * lda + mf));
        As[(mf + 0) * SA + k] = x.x;
        As[(mf + 1) * SA + k] = x.y;
        As[(mf + 2) * SA + k] = x.z;
        As[(mf + 3) * SA + k] = x.w;
    }
}
// As[m][k] = tf(A[k*lda + moff + m])  (transposed source, 64 rows)
__device__ __forceinline__ void fillAT64(const float* __restrict__ A, int lda,
                                         int moff, float* __restrict__ As) {
#pragma unroll
    for (int i = 0; i < 4; i++) {
        int idx = threadIdx.x + 512 * i;
        int k = idx >> 4, mf = (idx & 15) * 4;
        float4 x = tf4(*(const float4*)(A + k * lda + moff + mf));
        As[(mf + 0) * SA + k] = x.x;
        As[(mf + 1) * SA + k] = x.y;
        As[(mf + 2) * SA + k] = x.z;
        As[(mf + 3) * SA + k] = x.w;
    }
}
__device__ __forceinline__ void fillB(const float* __restrict__ B, int ldb,
                                      float* __restrict__ Bs) {
#pragma unroll
    for (int i = 0; i < 8; i++) {
        int idx = threadIdx.x + 512 * i;
        int k = idx >> 5, nf = (idx & 31) * 4;
        *(float4*)(Bs + k * SBN + nf) = tf4(*(const float4*)(B + k * ldb + nf));
    }
}
// Bs[k][n] = tf(B1[k*128+n] + B2[k*128+n])
__device__ __forceinline__ void fillB2(const float* __restrict__ B1,
                                       const float* __restrict__ B2,
                                       float* __restrict__ Bs) {
#pragma unroll
    for (int i = 0; i < 8; i++) {
        int idx = threadIdx.x + 512 * i;
        int k = idx >> 5, nf = (idx & 31) * 4;
        float4 x = *(const float4*)(B1 + k * 128 + nf);
        float4 y = *(const float4*)(B2 + k * 128 + nf);
        x.x += y.x; x.y += y.y; x.z += y.z; x.w += y.w;
        *(float4*)(Bs + k * SBN + nf) = tf4(x);
    }
}
// Bs[k][n] = tf(B[n*ldb + k])  (B transposed: V^T)
__device__ __forceinline__ void fillBT(const float* __restrict__ B, int ldb,
                                       float* __restrict__ Bs) {
#pragma unroll
    for (int i = 0; i < 8; i++) {
        int idx = threadIdx.x + 512 * i;
        int n = idx >> 5, kf = (idx & 31) * 4;
        float4 x = tf4(*(const float4*)(B + n * ldb + kf));
        Bs[(kf + 0) * SBN + n] = x.x;
        Bs[(kf + 1) * SBN + n] = x.y;
        Bs[(kf + 2) * SBN + n] = x.z;
        Bs[(kf + 3) * SBN + n] = x.w;
    }
}

// ---------------- compute cores ----------------
__device__ __forceinline__ void compute128(const float* __restrict__ As,
                                           const float* __restrict__ Bs,
                                           float acc[2][4][4]) {
    const int lane = threadIdx.x & 31, warp = threadIdx.x >> 5;
    const int mr = (warp & 3) * 32, nc = (warp >> 2) * 32;
    const int ar = lane >> 2, ac = lane & 3;
    const int bk = lane & 3,  bn = lane >> 2;
#pragma unroll
    for (int kk = 0; kk < 128; kk += 8) {
        float a[2][4];
#pragma unroll
        for (int i = 0; i < 2; i++) {
            const float* p = As + (mr + 16 * i + ar) * SA + kk + ac;
            a[i][0] = p[0]; a[i][1] = p[8 * SA]; a[i][2] = p[4]; a[i][3] = p[8 * SA + 4];
        }
#pragma unroll
        for (int j = 0; j < 4; j++) {
            const float* p = Bs + (kk + bk) * SBN + nc + 8 * j + bn;
            float b[2] = { p[0], p[4 * SBN] };
            mma8(acc[0][j], a[0], b);
            mma8(acc[1][j], a[1], b);
        }
    }
}
__device__ __forceinline__ void compute64(const float* __restrict__ As,
                                          const float* __restrict__ Bs,
                                          float acc[4][4]) {
    const int lane = threadIdx.x & 31, warp = threadIdx.x >> 5;
    const int mr = (warp & 3) * 16, nc = (warp >> 2) * 32;
    const int ar = lane >> 2, ac = lane & 3;
    const int bk = lane & 3,  bn = lane >> 2;
#pragma unroll
    for (int kk = 0; kk < 128; kk += 8) {
        float a[4];
        const float* p = As + (mr + ar) * SA + kk + ac;
        a[0] = p[0]; a[1] = p[8 * SA]; a[2] = p[4]; a[3] = p[8 * SA + 4];
#pragma unroll
        for (int j = 0; j < 4; j++) {
            const float* qp = Bs + (kk + bk) * SBN + nc + 8 * j + bn;
            float b[2] = { qp[0], qp[4 * SBN] };
            mma8(acc[j], a, b);
        }
    }
}

// ---------------- epilogues ----------------
__device__ __forceinline__ void epi128(float* __restrict__ C,
                                       const float* __restrict__ a1,
                                       float acc[2][4][4]) {
    const int lane = threadIdx.x & 31, warp = threadIdx.x >> 5;
    const int r0 = (warp & 3) * 32 + (lane >> 2);
    const int c0 = (warp >> 2) * 32 + 2 * (lane & 3);
#pragma unroll
    for (int i = 0; i < 2; i++)
#pragma unroll
        for (int j = 0; j < 4; j++) {
            int r = r0 + 16 * i, c = c0 + 8 * j;
            float2 lo = make_float2(acc[i][j][0], acc[i][j][1]);
            float2 hi = make_float2(acc[i][j][2], acc[i][j][3]);
            if (a1) {
                float2 x = *(const float2*)(a1 + r * 128 + c);
                float2 y = *(const float2*)(a1 + (r + 8) * 128 + c);
                lo.x += x.x; lo.y += x.y; hi.x += y.x; hi.y += y.y;
            }
            *(float2*)(C + r * 128 + c)       = lo;
            *(float2*)(C + (r + 8) * 128 + c) = hi;
        }
}
__device__ __forceinline__ void epi64(float* __restrict__ C,
                                      const float* __restrict__ a1,
                                      const float* __restrict__ a2,
                                      float acc[4][4]) {
    const int lane = threadIdx.x & 31, warp = threadIdx.x >> 5;
    const int r0 = (warp & 3) * 16 + (lane >> 2);
    const int c0 = (warp >> 2) * 32 + 2 * (lane & 3);
#pragma unroll
    for (int j = 0; j < 4; j++) {
        int c = c0 + 8 * j;
        float2 lo = make_float2(acc[j][0], acc[j][1]);
        float2 hi = make_float2(acc[j][2], acc[j][3]);
        if (a1) {
            float2 x = *(const float2*)(a1 + r0 * 128 + c);
            float2 y = *(const float2*)(a1 + (r0 + 8) * 128 + c);
            lo.x += x.x; lo.y += x.y; hi.x += y.x; hi.y += y.y;
        }
        if (a2) {
            float2 x = *(const float2*)(a2 + r0 * 128 + c);
            float2 y = *(const float2*)(a2 + (r0 + 8) * 128 + c);
            lo.x += x.x; lo.y += x.y; hi.x += y.x; hi.y += y.y;
        }
        *(float2*)(C + r0 * 128 + c)       = lo;
        *(float2*)(C + (r0 + 8) * 128 + c) = hi;
    }
}
// T (64x128) -> As layout (tf32), for chained GEMM
__device__ __forceinline__ void storeT64(float* __restrict__ As, float acc[4][4]) {
    const int lane = threadIdx.x & 31, warp = threadIdx.x >> 5;
    const int r0 = (warp & 3) * 16 + (lane >> 2);
    const int c0 = (warp >> 2) * 32 + 2 * (lane & 3);
#pragma unroll
    for (int j = 0; j < 4; j++) {
        int c = c0 + 8 * j;
        As[r0 * SA + c]           = tf(acc[j][0]);
        As[r0 * SA + c + 1]       = tf(acc[j][1]);
        As[(r0 + 8) * SA + c]     = tf(acc[j][2]);
        As[(r0 + 8) * SA + c + 1] = tf(acc[j][3]);
    }
}
__device__ __forceinline__ void zero4(float a[4][4]) {
#pragma unroll
    for (int j = 0; j < 4; j++)
#pragma unroll
        for (int r = 0; r < 4; r++) a[j][r] = 0.0f;
}

// ---------------- the single persistent kernel ----------------
__global__ __launch_bounds__(512, 1) void k_all(const float* __restrict__ Z,
                                                const float* __restrict__ v,
                                                const float* __restrict__ q,
                                                float* __restrict__ out) {
    extern __shared__ float sm[];
    const int bid = blockIdx.x, tid = threadIdx.x;

    __shared__ unsigned s_base;
    if (tid == 0) s_base = *(volatile unsigned*)&g_gen;
    __syncthreads();
    const unsigned base = s_base;
    unsigned bar = 0;

    // ---- phase 0: G0 partials: part[chunk,b] = Zc^T Zc ----
    {
        float* As = sm; float* Bs = sm + 128 * SA;
        int chunk = bid >> 3, b = bid & 7;
        const float* Zc = Z + (b * 2048 + chunk * 128) * 128;
        fillAT128(Zc, 128, As);
        fillB(Zc, 128, Bs);
        __syncthreads();
        float acc[2][4][4]; zero4(acc[0]); zero4(acc[1]);
        compute128(As, Bs, acc);
        epi128(g_part + bid * MAT, 0, acc);
    }
    gsync(base + ++bar);

    // ---- phase 1: reduce partials -> G[0] ----
#pragma unroll
    for (int i = 0; i < 2; i++) {
        int e = bid * 1024 + tid + 512 * i;          // 131072 total
        int b = e >> 14, idx = e & 16383;
        float s = 0.0f;
#pragma unroll
        for (int c = 0; c < 16; c++) s += g_part[(c * 8 + b) * MAT + idx];
        g_G[0][e] = s;
    }
    gsync(base + ++bar);

    int cur = 0;
    for (int l = 0; l < 4; l++) {
        // ---- TW: per (j,b,mh): T = Q_j G, W_j = T V_j^T ----
        {
            float* As  = sm;
            float* BsG = sm + 64 * SA;
            float* BsV = BsG + 128 * SBN;
            int j = bid & 7, b = (bid >> 3) & 7, mh = bid >> 6;
            const float* Qp = q + (l * 8 + j) * MAT + mh * 64 * 128;
            fillA64(Qp, 128, As);
            fillB(g_G[cur] + b * MAT, 128, BsG);
            fillBT(v + (l * 8 + j) * MAT, 128, BsV);
            __syncthreads();
            float acc[4][4]; zero4(acc);
            compute64(As, BsG, acc);
            __syncthreads();
            storeT64(As, acc);
            __syncthreads();
            zero4(acc);
            compute64(As, BsV, acc);
            epi64(g_Wp + (b * 8 + j) * MAT + mh * 64 * 128, 0, 0, acc);
        }
        gsync(base + ++bar);

        // ---- Wsum: W' = SCALE * sum_j W_j ; layer 0: R = W' ----
#pragma unroll
        for (int i = 0; i < 2; i++) {
            int e = bid * 1024 + tid + 512 * i;
            int b = e >> 14, idx = e & 16383;
            float s = 0.0f;
#pragma unroll
            for (int j = 0; j < 8; j++) s += g_Wp[(b * 8 + j) * MAT + idx];
            s *= SCALE;
            g_Wq[e] = s;
            if (l == 0) g_R[e] = s;
        }
        gsync(base + ++bar);

        // ---- C1: bid 0..15: U slab = G slab @ W' (needed when l<3)
        //          bid 16..31: R slab = R + W' + R@W'  (skip at l==0: R=W')
        if (bid < 16 && l < 3) {
            int mh = bid & 1, b = bid >> 1;
            float* As = sm; float* Bs = sm + 64 * SA;
            fillA64(g_G[cur] + b * MAT + mh * 64 * 128, 128, As);
            fillB(g_Wq + b * MAT, 128, Bs);
            __syncthreads();
            float acc[4][4]; zero4(acc);
            compute64(As, Bs, acc);
            epi64(g_U + b * MAT + mh * 64 * 128, 0, 0, acc);
        } else if (bid >= 16 && bid < 32 && l > 0) {
            int idx = bid - 16, mh = idx & 1, b = idx >> 1;
            float* As = sm; float* Bs = sm + 64 * SA;
            float* Rp = g_R + b * MAT + mh * 64 * 128;
            fillA64(Rp, 128, As);
            fillB(g_Wq + b * MAT, 128, Bs);
            __syncthreads();
            float acc[4][4]; zero4(acc);
            compute64(As, Bs, acc);
            epi64(Rp, Rp, g_Wq + b * MAT + mh * 64 * 128, acc);
        }
        gsync(base + ++bar);

        // ---- C2 (l<3): Gnext slab = W'^T slab @ (G+U) + G + U ----
        if (l < 3) {
            if (bid < 16) {
                int mh = bid & 1, b = bid >> 1;
                float* As = sm; float* Bs = sm + 64 * SA;
                fillAT64(g_Wq + b * MAT, 128, mh * 64, As);
                fillB2(g_G[cur] + b * MAT, g_U + b * MAT, Bs);
                __syncthreads();
                float acc[4][4]; zero4(acc);
                compute64(As, Bs, acc);
                epi64(g_G[cur ^ 1] + b * MAT + mh * 64 * 128,
                      g_G[cur]     + b * MAT + mh * 64 * 128,
                      g_U          + b * MAT + mh * 64 * 128, acc);
            }
            gsync(base + ++bar);
            cur ^= 1;
        }
    }

    // ---- out: out_tile = Z_tile R + Z_tile ----
    {
        float* As = sm; float* Bs = sm + 128 * SA;
        int tile = bid >> 3, b = bid & 7;
        const float* Zt = Z + (b * 2048 + tile * 128) * 128;
        fillA128(Zt, 128, As);
        fillB(g_R + b * MAT, 128, Bs);
        __syncthreads();
        float acc[2][4][4]; zero4(acc[0]); zero4(acc[1]);
        compute128(As, Bs, acc);
        epi128(out + (b * 2048 + tile * 128) * 128, Zt, acc);
    }
}

// ---------------- host ----------------
#define SMEM_BYTES ((64 * SA + 2 * 128 * SBN) * 4)   // 173056 B (max phase: TW)

extern "C" void kernel_launch(void* const* d_in, const int* in_sizes, int n_in,
                              void* d_out, int out_size) {
    const float* Z = (const float*)d_in[0];
    const float* v = (const float*)d_in[1];
    const float* q = (const float*)d_in[2];
    float* out = (float*)d_out;

    cudaFuncSetAttribute(k_all, cudaFuncAttributeMaxDynamicSharedMemorySize, SMEM_BYTES);
    k_all<<<NB, 512, SMEM_BYTES>>>(Z, v, q, out);
}